// round 1
// baseline (speedup 1.0000x reference)
#include <cuda_runtime.h>

#define FULL_MASK 0xFFFFFFFFu
static constexpr int HID = 32;
static constexpr int TT = 1024;
static constexpr int WARPS_PER_CTA = 8;

// ---- packed f32x2 helpers (sm_103a; ptxas never auto-fuses these) ----
__device__ __forceinline__ unsigned long long pack2(float lo, float hi) {
    unsigned long long r;
    asm("mov.b64 %0, {%1, %2};" : "=l"(r) : "f"(lo), "f"(hi));
    return r;
}
__device__ __forceinline__ void unpack2(unsigned long long v, float& lo, float& hi) {
    asm("mov.b64 {%0, %1}, %2;" : "=f"(lo), "=f"(hi) : "l"(v));
}
__device__ __forceinline__ unsigned long long fma2(unsigned long long a,
                                                   unsigned long long b,
                                                   unsigned long long c) {
    unsigned long long d;
    asm("fma.rn.f32x2 %0, %1, %2, %3;" : "=l"(d) : "l"(a), "l"(b), "l"(c));
    return d;
}
__device__ __forceinline__ float ex2f(float x) {
    float r; asm("ex2.approx.f32 %0, %1;" : "=f"(r) : "f"(x)); return r;
}
__device__ __forceinline__ float rcpf(float x) {
    float r; asm("rcp.approx.f32 %0, %1;" : "=f"(r) : "f"(x)); return r;
}
// sigmoid(x) = 1 / (1 + 2^(-x*log2(e)))  — ex2/rcp approx are ~2^-22 rel err
__device__ __forceinline__ float fast_sigmoid(float x) {
    return rcpf(1.0f + ex2f(-1.4426950408889634f * x));
}
// tanh(x) = 2*sigmoid(2x) - 1
__device__ __forceinline__ float fast_tanh(float x) {
    float r = rcpf(1.0f + ex2f(-2.8853900817779268f * x));
    return fmaf(2.0f, r, -1.0f);
}

// One warp per batch element. lane j owns hidden unit j.
// Per lane, W_hh rows for the 4 gates at hidden index j are held packed in
// registers as (i,f) and (g,o) f32x2 pairs: 128 registers of weights.
// h is broadcast per step via a per-warp SMEM ping-pong, stored DUPLICATED
// (h_k, h_k) so a single LDS.128 yields two ready-packed f32x2 multiplicands.
__global__ void __launch_bounds__(WARPS_PER_CTA * 32)
lstm_kernel(const float* __restrict__ x,
            const float* __restrict__ W_ih,
            const float* __restrict__ W_hh,
            const float* __restrict__ b_ih,
            const float* __restrict__ b_hh,
            const float* __restrict__ fc_W,
            const float* __restrict__ fc_b,
            float* __restrict__ out, int B)
{
    __shared__ __align__(16) float2 hbuf[WARPS_PER_CTA][2][HID];
    const int warp = threadIdx.x >> 5;
    const int lane = threadIdx.x & 31;
    const int b = blockIdx.x * WARPS_PER_CTA + warp;
    if (b >= B) return;   // whole warp exits together (b is per-warp)

    // Gate order (PyTorch): rows [0:32)=i, [32:64)=f, [64:96)=g, [96:128)=o
    unsigned long long Wif[HID], Wgo[HID];
    #pragma unroll
    for (int k = 0; k < HID; ++k) {
        Wif[k] = pack2(W_hh[(0 * HID + lane) * HID + k],
                       W_hh[(1 * HID + lane) * HID + k]);
        Wgo[k] = pack2(W_hh[(2 * HID + lane) * HID + k],
                       W_hh[(3 * HID + lane) * HID + k]);
    }
    const unsigned long long wih_if = pack2(W_ih[0 * HID + lane], W_ih[1 * HID + lane]);
    const unsigned long long wih_go = pack2(W_ih[2 * HID + lane], W_ih[3 * HID + lane]);
    const unsigned long long bias_if =
        pack2(b_ih[0 * HID + lane] + b_hh[0 * HID + lane],
              b_ih[1 * HID + lane] + b_hh[1 * HID + lane]);
    const unsigned long long bias_go =
        pack2(b_ih[2 * HID + lane] + b_hh[2 * HID + lane],
              b_ih[3 * HID + lane] + b_hh[3 * HID + lane]);

    float h = 0.0f, c = 0.0f;
    const float* xrow = x + (size_t)b * TT;   // x is [B, T, 1]

    for (int t0 = 0; t0 < TT; t0 += 32) {
        // one coalesced 128B read per warp per 32 steps
        const float xbuf = xrow[t0 + lane];
        #pragma unroll 4
        for (int s = 0; s < 32; ++s) {
            const float xv = __shfl_sync(FULL_MASK, xbuf, s);
            const unsigned long long xv2 = pack2(xv, xv);
            // gates init = x*W_ih + (b_ih + b_hh)
            unsigned long long acc_if = fma2(xv2, wih_if, bias_if);
            unsigned long long acc_go = fma2(xv2, wih_go, bias_go);

            // broadcast h through per-warp ping-pong buffer
            float2* buf = hbuf[warp][s & 1];
            buf[lane] = make_float2(h, h);
            __syncwarp();
            const ulonglong2* b2 = reinterpret_cast<const ulonglong2*>(buf);
            #pragma unroll
            for (int k2 = 0; k2 < HID / 2; ++k2) {
                const ulonglong2 hk = b2[k2];     // LDS.128 broadcast, N=1
                acc_if = fma2(Wif[2 * k2],     hk.x, acc_if);
                acc_go = fma2(Wgo[2 * k2],     hk.x, acc_go);
                acc_if = fma2(Wif[2 * k2 + 1], hk.y, acc_if);
                acc_go = fma2(Wgo[2 * k2 + 1], hk.y, acc_go);
            }

            float ai, af, ag, ao;
            unpack2(acc_if, ai, af);
            unpack2(acc_go, ag, ao);
            const float ig = fast_sigmoid(ai);
            const float fg = fast_sigmoid(af);
            const float gg = fast_tanh(ag);
            const float og = fast_sigmoid(ao);
            c = fmaf(fg, c, ig * gg);
            h = og * fast_tanh(c);
        }
    }

    // out[b] = h . fc_W + fc_b  (warp reduce)
    float v = h * fc_W[lane];
    #pragma unroll
    for (int off = 16; off; off >>= 1)
        v += __shfl_xor_sync(FULL_MASK, v, off);
    if (lane == 0) out[b] = v + fc_b[0];
}

extern "C" void kernel_launch(void* const* d_in, const int* in_sizes, int n_in,
                              void* d_out, int out_size) {
    const float* x    = (const float*)d_in[0];
    const float* W_ih = (const float*)d_in[1];
    const float* W_hh = (const float*)d_in[2];
    const float* b_ih = (const float*)d_in[3];
    const float* b_hh = (const float*)d_in[4];
    const float* fc_W = (const float*)d_in[5];
    const float* fc_b = (const float*)d_in[6];
    float* out = (float*)d_out;

    const int B = in_sizes[0] / TT;           // x is B*T*1 elements
    const int ctas = (B + WARPS_PER_CTA - 1) / WARPS_PER_CTA;
    lstm_kernel<<<ctas, WARPS_PER_CTA * 32>>>(x, W_ih, W_hh, b_ih, b_hh,
                                              fc_W, fc_b, out, B);
}

// round 2
// speedup vs baseline: 1.2097x; 1.2097x over previous
#include <cuda_runtime.h>

#define FULL_MASK 0xFFFFFFFFu
static constexpr int HID = 32;
static constexpr int TT = 1024;
static constexpr int WARPS_PER_CTA = 4;   // 128-thread CTAs -> 3 CTAs/SM at 166 regs

// ---- packed f32x2 helpers (sm_103a; ptxas never auto-fuses these) ----
__device__ __forceinline__ unsigned long long pack2(float lo, float hi) {
    unsigned long long r;
    asm("mov.b64 %0, {%1, %2};" : "=l"(r) : "f"(lo), "f"(hi));
    return r;
}
__device__ __forceinline__ void unpack2(unsigned long long v, float& lo, float& hi) {
    asm("mov.b64 {%0, %1}, %2;" : "=f"(lo), "=f"(hi) : "l"(v));
}
__device__ __forceinline__ unsigned long long fma2(unsigned long long a,
                                                   unsigned long long b,
                                                   unsigned long long c) {
    unsigned long long d;
    asm("fma.rn.f32x2 %0, %1, %2, %3;" : "=l"(d) : "l"(a), "l"(b), "l"(c));
    return d;
}
__device__ __forceinline__ float ex2f(float x) {
    float r; asm("ex2.approx.f32 %0, %1;" : "=f"(r) : "f"(x)); return r;
}
__device__ __forceinline__ float rcpf(float x) {
    float r; asm("rcp.approx.f32 %0, %1;" : "=f"(r) : "f"(x)); return r;
}
// sigmoid(x) = 1 / (1 + 2^(-x*log2(e)))  — ex2/rcp approx are ~2^-22 rel err
__device__ __forceinline__ float fast_sigmoid(float x) {
    return rcpf(1.0f + ex2f(-1.4426950408889634f * x));
}
// tanh(x) = 2*sigmoid(2x) - 1
__device__ __forceinline__ float fast_tanh(float x) {
    float r = rcpf(1.0f + ex2f(-2.8853900817779268f * x));
    return fmaf(2.0f, r, -1.0f);
}

// One warp per batch element. lane j owns hidden unit j.
// Per lane, W_hh rows for the 4 gates at hidden index j are held packed in
// registers as (i,f) and (g,o) f32x2 pairs: 128 registers of weights.
// h is broadcast per step via a per-warp SMEM ping-pong, stored DUPLICATED
// (h_k, h_k) so a single LDS.128 yields two ready-packed f32x2 multiplicands.
__global__ void __launch_bounds__(WARPS_PER_CTA * 32)
lstm_kernel(const float* __restrict__ x,
            const float* __restrict__ W_ih,
            const float* __restrict__ W_hh,
            const float* __restrict__ b_ih,
            const float* __restrict__ b_hh,
            const float* __restrict__ fc_W,
            const float* __restrict__ fc_b,
            float* __restrict__ out, int B)
{
    __shared__ __align__(16) float2 hbuf[WARPS_PER_CTA][2][HID];
    const int warp = threadIdx.x >> 5;
    const int lane = threadIdx.x & 31;
    const int b = blockIdx.x * WARPS_PER_CTA + warp;
    if (b >= B) return;   // whole warp exits together (b is per-warp)

    // Gate order (PyTorch): rows [0:32)=i, [32:64)=f, [64:96)=g, [96:128)=o
    unsigned long long Wif[HID], Wgo[HID];
    #pragma unroll
    for (int k = 0; k < HID; ++k) {
        Wif[k] = pack2(W_hh[(0 * HID + lane) * HID + k],
                       W_hh[(1 * HID + lane) * HID + k]);
        Wgo[k] = pack2(W_hh[(2 * HID + lane) * HID + k],
                       W_hh[(3 * HID + lane) * HID + k]);
    }
    const unsigned long long wih_if = pack2(W_ih[0 * HID + lane], W_ih[1 * HID + lane]);
    const unsigned long long wih_go = pack2(W_ih[2 * HID + lane], W_ih[3 * HID + lane]);
    const unsigned long long bias_if =
        pack2(b_ih[0 * HID + lane] + b_hh[0 * HID + lane],
              b_ih[1 * HID + lane] + b_hh[1 * HID + lane]);
    const unsigned long long bias_go =
        pack2(b_ih[2 * HID + lane] + b_hh[2 * HID + lane],
              b_ih[3 * HID + lane] + b_hh[3 * HID + lane]);

    float h = 0.0f, c = 0.0f;
    const float* xrow = x + (size_t)b * TT;   // x is [B, T, 1]

    for (int t0 = 0; t0 < TT; t0 += 32) {
        // one coalesced 128B read per warp per 32 steps
        const float xbuf = xrow[t0 + lane];
        #pragma unroll 2
        for (int s = 0; s < 32; ++s) {
            const float xv = __shfl_sync(FULL_MASK, xbuf, s);
            const unsigned long long xv2 = pack2(xv, xv);
            // gates init = x*W_ih + (b_ih + b_hh)
            unsigned long long acc_if = fma2(xv2, wih_if, bias_if);
            unsigned long long acc_go = fma2(xv2, wih_go, bias_go);

            // broadcast h through per-warp ping-pong buffer
            float2* buf = hbuf[warp][s & 1];
            buf[lane] = make_float2(h, h);
            __syncwarp();
            const ulonglong2* b2 = reinterpret_cast<const ulonglong2*>(buf);
            #pragma unroll
            for (int k2 = 0; k2 < HID / 2; ++k2) {
                const ulonglong2 hk = b2[k2];     // LDS.128 broadcast, N=1
                acc_if = fma2(Wif[2 * k2],     hk.x, acc_if);
                acc_go = fma2(Wgo[2 * k2],     hk.x, acc_go);
                acc_if = fma2(Wif[2 * k2 + 1], hk.y, acc_if);
                acc_go = fma2(Wgo[2 * k2 + 1], hk.y, acc_go);
            }

            float ai, af, ag, ao;
            unpack2(acc_if, ai, af);
            unpack2(acc_go, ag, ao);
            const float ig = fast_sigmoid(ai);
            const float fg = fast_sigmoid(af);
            const float gg = fast_tanh(ag);
            const float og = fast_sigmoid(ao);
            c = fmaf(fg, c, ig * gg);
            h = og * fast_tanh(c);
        }
    }

    // out[b] = h . fc_W + fc_b  (warp reduce)
    float v = h * fc_W[lane];
    #pragma unroll
    for (int off = 16; off; off >>= 1)
        v += __shfl_xor_sync(FULL_MASK, v, off);
    if (lane == 0) out[b] = v + fc_b[0];
}

extern "C" void kernel_launch(void* const* d_in, const int* in_sizes, int n_in,
                              void* d_out, int out_size) {
    const float* x    = (const float*)d_in[0];
    const float* W_ih = (const float*)d_in[1];
    const float* W_hh = (const float*)d_in[2];
    const float* b_ih = (const float*)d_in[3];
    const float* b_hh = (const float*)d_in[4];
    const float* fc_W = (const float*)d_in[5];
    const float* fc_b = (const float*)d_in[6];
    float* out = (float*)d_out;

    const int B = in_sizes[0] / TT;           // x is B*T*1 elements
    const int ctas = (B + WARPS_PER_CTA - 1) / WARPS_PER_CTA;
    lstm_kernel<<<ctas, WARPS_PER_CTA * 32>>>(x, W_ih, W_hh, b_ih, b_hh,
                                              fc_W, fc_b, out, B);
}